// round 5
// baseline (speedup 1.0000x reference)
#include <cuda_runtime.h>
#include <cuda_bf16.h>

// Problem constants (fixed by the reference).
#define BB   2
#define DD   96
#define HH   96
#define WW   96
#define CIN  16
#define COUT 32
#define NK   27
#define GRIDVOL (BB*DD*HH*WW)      // 1,769,472

#define NBIN  27                   // all 27 offsets (center = bin 13)
#define NCAP  262144
#define CHUNK 64

#define CONV_BLOCKS  592
#define CONV_THREADS 256
#define TOTW (CONV_BLOCKS*(CONV_THREADS/32))   // 4736 warps
#define CWARPS 1184                // warps dedicated to center bin (~25%)
#define RWARPS (TOTW - CWARPS)     // 3552 warps over 26 off-center bins

typedef unsigned long long u64;

// Scratch (static __device__ arrays: allocation-free).
__device__ int  g_grid[GRIDVOL];               // voxel -> point id, -1 empty
__device__ u64  g_wc[NK * 16 * 2 * 8];         // [k][co2][s][ci2] f32x2 over ci
__device__ int  g_cnt[NBIN];
__device__ int2 g_pairs[(long)NBIN * NCAP];

// ---------------------------------------------------------------------------
// Packed f32x2 helpers (sm_103a FFMA2 path).
__device__ __forceinline__ u64 fma2(u64 a, u64 b, u64 c) {
    u64 d; asm("fma.rn.f32x2 %0, %1, %2, %3;" : "=l"(d) : "l"(a), "l"(b), "l"(c));
    return d;
}
__device__ __forceinline__ u64 mul2(u64 a, u64 b) {
    u64 d; asm("mul.rn.f32x2 %0, %1, %2;" : "=l"(d) : "l"(a), "l"(b));
    return d;
}
__device__ __forceinline__ u64 add2(u64 a, u64 b) {
    u64 d; asm("add.rn.f32x2 %0, %1, %2;" : "=l"(d) : "l"(a), "l"(b));
    return d;
}
__device__ __forceinline__ float hsum2(u64 a) {
    unsigned lo, hi;
    asm("mov.b64 {%0, %1}, %2;" : "=r"(lo), "=r"(hi) : "l"(a));
    return __uint_as_float(lo) + __uint_as_float(hi);
}
// 16-ci dot for ONE output channel; features & weights both ci-packed.
__device__ __forceinline__ float dotci(const ulonglong2& f0, const ulonglong2& f1,
                                       const ulonglong2& f2, const ulonglong2& f3,
                                       const u64* w8) {
    u64 s0 = mul2(f0.x, w8[0]);
    u64 s1 = mul2(f0.y, w8[1]);
    s0 = fma2(f1.x, w8[2], s0);
    s1 = fma2(f1.y, w8[3], s1);
    s0 = fma2(f2.x, w8[4], s0);
    s1 = fma2(f2.y, w8[5], s1);
    s0 = fma2(f3.x, w8[6], s0);
    s1 = fma2(f3.y, w8[7], s1);
    return hsum2(add2(s0, s1));
}
// Vectorized f32 reduction (sm_90+): 8 bytes per lane.
__device__ __forceinline__ void red2(float* p, float x, float y) {
    asm volatile("red.global.add.v2.f32 [%0], {%1, %2};"
                 :: "l"(p), "f"(x), "f"(y) : "memory");
}

// ---------------------------------------------------------------------------
__global__ void scatter_idx_kernel(const int4* __restrict__ idx, int n) {
    int p = blockIdx.x * blockDim.x + threadIdx.x;
    if (p < n) {
        int4 q = idx[p];  // b, z, y, x
        g_grid[((q.x * DD + q.y) * HH + q.z) * WW + q.w] = p;
    }
}

// conv_w [co][ci][kd][kh][kw] -> g_wc[k][co2][s][ci2] (f32x2 packed over ci).
// Also zeroes the bin counters.
__global__ void repack_w_kernel(const float* __restrict__ w) {
    int t = blockIdx.x * blockDim.x + threadIdx.x;   // 6912 entries
    if (blockIdx.x == 0 && threadIdx.x < NBIN) g_cnt[threadIdx.x] = 0;
    if (t < NK * 16 * 2 * 8) {
        int ci2 = t & 7;
        int s   = (t >> 3) & 1;
        int co2 = (t >> 4) & 15;
        int k   = t >> 8;
        int co  = co2 * 2 + s;
        float w0 = w[(co * CIN + 2*ci2    ) * NK + k];
        float w1 = w[(co * CIN + 2*ci2 + 1) * NK + k];
        g_wc[t] = ((u64)__float_as_uint(w1) << 32) | __float_as_uint(w0);
    }
}

// ---------------------------------------------------------------------------
// Build 27 pair lists (smem staging, one aggregated global atomic per bin).
// Lane l (<27) probes offset l; center (13) always hits its own voxel.
__global__ __launch_bounds__(256)
void probe_kernel(const int4* __restrict__ idx, int n) {
    __shared__ int  scnt[NBIN];
    __shared__ int  sbase[NBIN];
    __shared__ int2 srec[NBIN * CHUNK];

    int tid = threadIdx.x, lane = tid & 31, warp = tid >> 5;
    if (tid < NBIN) scnt[tid] = 0;
    __syncthreads();

    int dz = lane / 9 - 1, dy = (lane / 3) % 3 - 1, dx = lane % 3 - 1;
    int p0 = blockIdx.x * CHUNK + warp * (CHUNK / 8);

#pragma unroll
    for (int r = 0; r < CHUNK / 8; r++) {
        int p = p0 + r;
        if (p < n && lane < NBIN) {
            int4 q = __ldg(&idx[p]);
            int zz = q.y + dz, yy = q.z + dy, xx = q.w + dx;
            if ((unsigned)zz < (unsigned)DD &&
                (unsigned)yy < (unsigned)HH &&
                (unsigned)xx < (unsigned)WW) {
                int j = __ldg(&g_grid[((q.x * DD + zz) * HH + yy) * WW + xx]);
                if (j >= 0) {
                    int pos = atomicAdd(&scnt[lane], 1);
                    srec[lane * CHUNK + pos] = make_int2(j, p);
                }
            }
        }
    }
    __syncthreads();
    if (tid < NBIN) sbase[tid] = atomicAdd(&g_cnt[tid], scnt[tid]);
    __syncthreads();
    for (int t = tid; t < NBIN * CHUNK; t += 256) {
        int b = t / CHUNK, i = t % CHUNK;
        if (i < scnt[b]) g_pairs[(long)b * NCAP + sbase[b] + i] = srec[t];
    }
}

// ---------------------------------------------------------------------------
// Initialize output with bias (pure coalesced stores).
__global__ void bias_init_kernel(const float4* __restrict__ bias4,
                                 float4* __restrict__ out4, int n8) {
    int t = blockIdx.x * blockDim.x + threadIdx.x;
    if (t < n8) out4[t] = __ldg(&bias4[t & 7]);
}

// ---------------------------------------------------------------------------
// Pair conv: 16 lanes per point, lane handles 2 output channels; one
// red.v2.f32 per lane per point. 4 pairs per iteration for MLP.
__global__ __launch_bounds__(256)
void pair_conv_kernel(const ulonglong2* __restrict__ feat2,
                      float* __restrict__ out) {
    int lane = threadIdx.x & 31;
    int half = lane >> 4;          // which point of the pair-of-pairs
    int cl   = lane & 15;          // co pair index (co = 2*cl, 2*cl+1)
    int w = blockIdx.x * (CONV_THREADS / 32) + (threadIdx.x >> 5);

    int kk, slice, nwk;
    if (w < CWARPS) {              // center bin gets 25% of warps
        kk = 13; slice = w; nwk = CWARPS;
    } else {
        int w2 = w - CWARPS;
        int bp = w2 % 26;          // 0..25 -> offsets excluding 13
        slice = w2 / 26;
        nwk = (RWARPS - bp + 25) / 26;
        kk = bp < 13 ? bp : bp + 1;
    }

    u64 wk[16];                    // [0..7]=co even, [8..15]=co odd (ci-packed)
    const u64* wg = g_wc + ((long)(kk * 16 + cl) << 4);
#pragma unroll
    for (int i = 0; i < 16; i++) wk[i] = wg[i];

    int cnt = g_cnt[kk];
    const int2* pr = g_pairs + (long)kk * NCAP;
    int chunk = (((cnt + nwk - 1) / nwk) + 1) & ~1;   // even so int4 stays aligned
    int i0 = slice * chunk;
    int i1 = min(cnt, i0 + chunk);

    int i = i0;
    for (; i + 3 < i1; i += 4) {
        int4 ra = __ldg((const int4*)(pr + i));       // pairs i, i+1
        int4 rb = __ldg((const int4*)(pr + i + 2));   // pairs i+2, i+3
        int inA = half ? ra.z : ra.x,  oA = half ? ra.w : ra.y;
        int inB = half ? rb.z : rb.x,  oB = half ? rb.w : rb.y;
        const ulonglong2* fA = feat2 + ((long)inA << 2);
        const ulonglong2* fB = feat2 + ((long)inB << 2);
        ulonglong2 a0 = __ldg(fA),     a1 = __ldg(fA + 1),
                   a2 = __ldg(fA + 2), a3 = __ldg(fA + 3);
        ulonglong2 b0 = __ldg(fB),     b1 = __ldg(fB + 1),
                   b2 = __ldg(fB + 2), b3 = __ldg(fB + 3);
        float xA = dotci(a0, a1, a2, a3, wk);
        float yA = dotci(a0, a1, a2, a3, wk + 8);
        float xB = dotci(b0, b1, b2, b3, wk);
        float yB = dotci(b0, b1, b2, b3, wk + 8);
        red2(out + (long)oA * COUT + cl * 2, xA, yA);
        red2(out + (long)oB * COUT + cl * 2, xB, yB);
    }
    for (; i + 1 < i1; i += 2) {
        int4 ra = __ldg((const int4*)(pr + i));
        int inA = half ? ra.z : ra.x,  oA = half ? ra.w : ra.y;
        const ulonglong2* fA = feat2 + ((long)inA << 2);
        ulonglong2 a0 = __ldg(fA),     a1 = __ldg(fA + 1),
                   a2 = __ldg(fA + 2), a3 = __ldg(fA + 3);
        float xA = dotci(a0, a1, a2, a3, wk);
        float yA = dotci(a0, a1, a2, a3, wk + 8);
        red2(out + (long)oA * COUT + cl * 2, xA, yA);
    }
    if (i < i1) {                   // single leftover pair: half 0 only
        int2 r = __ldg(&pr[i]);
        const ulonglong2* fA = feat2 + ((long)r.x << 2);
        ulonglong2 a0 = __ldg(fA),     a1 = __ldg(fA + 1),
                   a2 = __ldg(fA + 2), a3 = __ldg(fA + 3);
        float xA = dotci(a0, a1, a2, a3, wk);
        float yA = dotci(a0, a1, a2, a3, wk + 8);
        if (half == 0) red2(out + (long)r.y * COUT + cl * 2, xA, yA);
    }
}

// ---------------------------------------------------------------------------
extern "C" void kernel_launch(void* const* d_in, const int* in_sizes, int n_in,
                              void* d_out, int out_size) {
    const float* feat = (const float*)d_in[0];   // [n,16] f32
    const int*   idx  = (const int*)d_in[1];     // [n,4]  i32
    const float* w    = (const float*)d_in[2];   // [32,16,3,3,3] f32
    const float* bias = (const float*)d_in[3];   // [32] f32
    int n = in_sizes[1] / 4;

    void* gptr = nullptr; cudaGetSymbolAddress(&gptr, g_grid);
    cudaMemsetAsync(gptr, 0xFF, sizeof(int) * (size_t)GRIDVOL);          // act 1

    scatter_idx_kernel<<<(n + 255) / 256, 256>>>((const int4*)idx, n);   // act 2
    repack_w_kernel<<<(NK * 16 * 2 * 8 + 255) / 256, 256>>>(w);          // act 3
    probe_kernel<<<(n + CHUNK - 1) / CHUNK, 256>>>((const int4*)idx, n); // act 4
    bias_init_kernel<<<(n * 8 + 255) / 256, 256>>>(
        (const float4*)bias, (float4*)d_out, n * 8);                     // act 5
    pair_conv_kernel<<<CONV_BLOCKS, CONV_THREADS>>>(
        (const ulonglong2*)feat, (float*)d_out);                         // act 6 (profiled)
}